// round 10
// baseline (speedup 1.0000x reference)
#include <cuda_runtime.h>
#include <cuda_bf16.h>
#include <cstdint>

// Locally-connected conv via mma.sync bf16 split precision, smem-staged weights.
// Per (h,w): D[o=64, b=32] = W[o,288] X[288,b] + bias.
// X smem tile [n=64][k=288]: rows 0-31 Xh, 32-63 Xl.
// W staged per 48-k chunk into A-tile [128 rows][48 k] bf16: rows 0-63 Wh, 64-127 Wl.
// Per k16-step/warp: 2 A-ldmatrix + 4 B-ldmatrix + 12 MMA.
// Out = WhXh + WhXl + WlXh (+bias); dropped WlXl ~ 2^-17.

#define B_    32
#define CIN_  32
#define IH_   64
#define IW_   64
#define COUT_ 64
#define OH_   64
#define OW_   64
#define KTOT  288
#define KROW  296              // X row stride (bf16), 592 B — LDSM conflict-free
#define KC    48               // k per W chunk
#define NCHK  6                // KTOT / KC
#define AROW  56               // A row stride (bf16), 112 B — LDSM conflict-free

#define XS_BYTES   (64 * KROW * 2)          // 37888
#define AW_BYTES   (128 * AROW * 2)         // 14336 per buffer
#define SMEM_DYN   (XS_BYTES + 2 * AW_BYTES)  // 66560

__device__ __forceinline__ uint32_t prmt_hi(uint32_t a, uint32_t b) {
    uint32_t r; asm("prmt.b32 %0, %1, %2, 0x7632;" : "=r"(r) : "r"(a), "r"(b)); return r;
}
__device__ __forceinline__ uint32_t lo_pack2(float fx, float fy) {
    float h0 = __uint_as_float(__float_as_uint(fx) & 0xFFFF0000u);
    float h1 = __uint_as_float(__float_as_uint(fy) & 0xFFFF0000u);
    __nv_bfloat162 p = __floats2bfloat162_rn(fx - h0, fy - h1);  // .x low 16
    return reinterpret_cast<uint32_t&>(p);
}
__device__ __forceinline__ void ldsm4(uint32_t& r0, uint32_t& r1, uint32_t& r2, uint32_t& r3,
                                      uint32_t a) {
    asm volatile("ldmatrix.sync.aligned.m8n8.x4.shared.b16 {%0,%1,%2,%3}, [%4];"
                 : "=r"(r0), "=r"(r1), "=r"(r2), "=r"(r3) : "r"(a));
}
__device__ __forceinline__ void mma16816(float* c,
                                         uint32_t a0, uint32_t a1, uint32_t a2, uint32_t a3,
                                         uint32_t b0, uint32_t b1) {
    asm volatile("mma.sync.aligned.m16n8k16.row.col.f32.bf16.bf16.f32 "
                 "{%0,%1,%2,%3}, {%4,%5,%6,%7}, {%8,%9}, {%0,%1,%2,%3};"
                 : "+f"(c[0]), "+f"(c[1]), "+f"(c[2]), "+f"(c[3])
                 : "r"(a0), "r"(a1), "r"(a2), "r"(a3), "r"(b0), "r"(b1));
}

__global__ __launch_bounds__(128)
void lc_conv_mma2(const float* __restrict__ x, const float* __restrict__ wgt,
                  const float* __restrict__ bias, float* __restrict__ out)
{
    extern __shared__ char smem[];
    __nv_bfloat16* xs = (__nv_bfloat16*)smem;                 // [64][KROW]
    char* aw0 = smem + XS_BYTES;
    char* aw1 = aw0 + AW_BYTES;

    const int w    = blockIdx.x, h = blockIdx.y;
    const int t    = threadIdx.x;
    const int wid  = t >> 5, lane = t & 31;
    const int gid  = lane >> 2;        // 0..7
    const int tig  = lane & 3;         // 0..3

    // ---- W staging geometry: 6 float4 units/thread/chunk; unit u covers
    //      row = u/12, float4 q = u%12 of the 48-float row-chunk.
    const float* wpos = wgt + (size_t)(h * OW_ + w) * COUT_ * KTOT;
    int g_off[6];       // global float offset (row*KTOT + 4q), add chunk k0
    int s_hi[6];        // smem byte offset of hi dst
#pragma unroll
    for (int i = 0; i < 6; i++) {
        int u = t + 128 * i;
        int row = u / 12;
        int q = u - 12 * row;
        g_off[i] = row * KTOT + 4 * q;
        s_hi[i]  = (row * AROW + 4 * q) * 2;
    }

    // ---- prefetch W chunk 0 (issue before X staging; latency overlaps it) ----
    float4 rv[6];
#pragma unroll
    for (int i = 0; i < 6; i++) rv[i] = *(const float4*)(wpos + g_off[i]);

    // ---- stage X (hi/lo bf16) into smem ----
    for (int u = t; u < B_ * CIN_ * 3; u += 128) {
        int b  = u & 31;
        int ci = u >> 5;
        int c  = ci / 3, i = ci - 3 * c;
        int row = h + i - 1;
        int k0  = c * 9 + i * 3;
        float v[3] = {0.f, 0.f, 0.f};
        if ((unsigned)row < IH_) {
            const float* xp = x + (((size_t)b * CIN_ + c) * IH_ + row) * IW_ + (w - 1);
#pragma unroll
            for (int j = 0; j < 3; j++)
                if ((unsigned)(w - 1 + j) < IW_) v[j] = xp[j];
        }
#pragma unroll
        for (int j = 0; j < 3; j++) {
            uint32_t ub = __float_as_uint(v[j]);
            unsigned short hs = (unsigned short)(ub >> 16);            // truncate-hi
            float hf = __uint_as_float(ub & 0xFFFF0000u);
            __nv_bfloat16 lo = __float2bfloat16(v[j] - hf);            // rn-lo
            xs[(size_t)b * KROW + k0 + j]        = reinterpret_cast<__nv_bfloat16&>(hs);
            xs[(size_t)(b + 32) * KROW + k0 + j] = lo;
        }
    }

    // ---- store W chunk 0 (convert in regs) ----
    {
        char* buf = aw0;
#pragma unroll
        for (int i = 0; i < 6; i++) {
            uint32_t h0 = prmt_hi(__float_as_uint(rv[i].x), __float_as_uint(rv[i].y));
            uint32_t h1 = prmt_hi(__float_as_uint(rv[i].z), __float_as_uint(rv[i].w));
            uint32_t l0 = lo_pack2(rv[i].x, rv[i].y);
            uint32_t l1 = lo_pack2(rv[i].z, rv[i].w);
            *(uint2*)(buf + s_hi[i])                 = make_uint2(h0, h1);
            *(uint2*)(buf + s_hi[i] + 64 * AROW * 2) = make_uint2(l0, l1);
        }
    }
    __syncthreads();

    // ---- LDSM lane addressing ----
    // B (X): matrices (n0-7,k0-7),(n0-7,k8-15),(n8-15,k0-7),(n8-15,k8-15)
    uint32_t lds_b[4];
    {
        uint32_t base = (uint32_t)__cvta_generic_to_shared(xs);
        int nrow = 8 * ((lane >> 4) & 1) + (lane & 7);
        int kadd = 8 * ((lane >> 3) & 1);
#pragma unroll
        for (int jp = 0; jp < 4; jp++)
            lds_b[jp] = base + (uint32_t)(16 * jp + nrow) * (KROW * 2) + kadd * 2;
    }
    // A (W): matrices (r0-7,k0-7),(r8-15,k0-7),(r0-7,k8-15),(r8-15,k8-15)
    uint32_t a_off;
    {
        int arow = (wid * 16) + (lane & 7) + 8 * ((lane >> 3) & 1);
        int ak16 = (lane >> 4) & 1;
        a_off = (uint32_t)arow * (AROW * 2) + (uint32_t)ak16 * 16;
    }
    const uint32_t aw_sm[2] = { (uint32_t)__cvta_generic_to_shared(aw0),
                                (uint32_t)__cvta_generic_to_shared(aw1) };

    float acc1[8][4];   // Wh x n-tiles 0..7 (Xh | Xl)
    float acc2[4][4];   // Wl x n-tiles 0..3 (Xh)
#pragma unroll
    for (int j = 0; j < 8; j++)
#pragma unroll
        for (int q = 0; q < 4; q++) acc1[j][q] = 0.f;
#pragma unroll
    for (int j = 0; j < 4; j++)
#pragma unroll
        for (int q = 0; q < 4; q++) acc2[j][q] = 0.f;

    // ---- main loop over 48-k chunks ----
#pragma unroll 1
    for (int ck = 0; ck < NCHK; ck++) {
        // prefetch next chunk early
        if (ck + 1 < NCHK) {
            int k0 = (ck + 1) * KC;
#pragma unroll
            for (int i = 0; i < 6; i++) rv[i] = *(const float4*)(wpos + g_off[i] + k0);
        }

        const uint32_t abase = aw_sm[ck & 1] + a_off;
#pragma unroll
        for (int s = 0; s < 3; s++) {
            uint32_t ah0, ah1, ah2, ah3, al0, al1, al2, al3;
            ldsm4(ah0, ah1, ah2, ah3, abase + s * 32);
            ldsm4(al0, al1, al2, al3, abase + 64 * (AROW * 2) + s * 32);

            uint32_t bb[16];
            uint32_t koff = (uint32_t)(ck * 3 + s) * 32;
#pragma unroll
            for (int jp = 0; jp < 4; jp++)
                ldsm4(bb[4 * jp], bb[4 * jp + 1], bb[4 * jp + 2], bb[4 * jp + 3],
                      lds_b[jp] + koff);

#pragma unroll
            for (int j = 0; j < 8; j++) {
                uint32_t b0 = bb[(j >> 1) * 4 + (j & 1) * 2];
                uint32_t b1 = bb[(j >> 1) * 4 + (j & 1) * 2 + 1];
                mma16816(acc1[j], ah0, ah1, ah2, ah3, b0, b1);
            }
#pragma unroll
            for (int j = 0; j < 4; j++) {
                uint32_t b0 = bb[(j >> 1) * 4 + (j & 1) * 2];
                uint32_t b1 = bb[(j >> 1) * 4 + (j & 1) * 2 + 1];
                mma16816(acc2[j], al0, al1, al2, al3, b0, b1);
            }
        }

        if (ck + 1 < NCHK) {
            char* buf = ((ck + 1) & 1) ? aw1 : aw0;
#pragma unroll
            for (int i = 0; i < 6; i++) {
                uint32_t h0 = prmt_hi(__float_as_uint(rv[i].x), __float_as_uint(rv[i].y));
                uint32_t h1 = prmt_hi(__float_as_uint(rv[i].z), __float_as_uint(rv[i].w));
                uint32_t l0 = lo_pack2(rv[i].x, rv[i].y);
                uint32_t l1 = lo_pack2(rv[i].z, rv[i].w);
                *(uint2*)(buf + s_hi[i])                 = make_uint2(h0, h1);
                *(uint2*)(buf + s_hi[i] + 64 * AROW * 2) = make_uint2(l0, l1);
            }
            __syncthreads();
        }
    }

    // ---- epilogue: combine products + bias, store ----
    const int o_lo = wid * 16 + gid;
    const int o_hi = o_lo + 8;
    const float bias_lo = bias[(o_lo * OH_ + h) * OW_ + w];
    const float bias_hi = bias[(o_hi * OH_ + h) * OW_ + w];

#pragma unroll
    for (int j = 0; j < 4; j++) {
        int b = 8 * j + 2 * tig;
        float v00 = acc1[j][0] + acc1[j + 4][0] + acc2[j][0] + bias_lo;  // (o_lo, b)
        float v01 = acc1[j][1] + acc1[j + 4][1] + acc2[j][1] + bias_lo;  // (o_lo, b+1)
        float v10 = acc1[j][2] + acc1[j + 4][2] + acc2[j][2] + bias_hi;  // (o_hi, b)
        float v11 = acc1[j][3] + acc1[j + 4][3] + acc2[j][3] + bias_hi;  // (o_hi, b+1)
        size_t p00 = (((size_t)b * COUT_ + o_lo) * OH_ + h) * OW_ + w;
        size_t p01 = (((size_t)(b + 1) * COUT_ + o_lo) * OH_ + h) * OW_ + w;
        out[p00] = v00;
        out[p01] = v01;
        out[p00 + (size_t)8 * OH_ * OW_] = v10;   // o_hi = o_lo + 8
        out[p01 + (size_t)8 * OH_ * OW_] = v11;
    }
}

extern "C" void kernel_launch(void* const* d_in, const int* in_sizes, int n_in,
                              void* d_out, int out_size)
{
    const float* x    = (const float*)d_in[0];   // [32,32,64,64]
    const float* wgt  = (const float*)d_in[1];   // [64,64,64,32,3,3]
    const float* bias = (const float*)d_in[2];   // [64,64,64]
    float* out = (float*)d_out;                  // [32,64,64,64]

    cudaFuncSetAttribute(lc_conv_mma2, cudaFuncAttributeMaxDynamicSharedMemorySize, SMEM_DYN);
    dim3 grid(OW_, OH_);
    lc_conv_mma2<<<grid, 128, SMEM_DYN>>>(x, wgt, bias, out);
}

// round 11
// speedup vs baseline: 1.5924x; 1.5924x over previous
#include <cuda_runtime.h>
#include <cuda_bf16.h>
#include <cstdint>

// Locally-connected conv via mma.sync bf16 split precision.
// CTA = 256 threads = 2 position-groups (w0, w0+1), sharing X staging.
// Per group: D[o=64,b=32] = W X + bias; B tile [n=64][k=288] (rows 0-31 Xh, 32-63 Xl).
// A (W) streamed per 48-k chunk, single smem buffer + reg prefetch, group-local barriers.
// Out = WhXh + WhXl + WlXh (+bias); dropped WlXl ~ 2^-17.

#define B_    32
#define CIN_  32
#define IH_   64
#define IW_   64
#define COUT_ 64
#define OH_   64
#define OW_   64
#define KTOT  288
#define KROW  296              // B row stride (bf16) = 592 B, LDSM conflict-free
#define KC    48
#define NCHK  6
#define AROW  56               // A row stride (bf16) = 112 B, LDSM conflict-free

#define XS_BYTES (64 * KROW * 2)   // 37888 per group
#define AW_BYTES (128 * AROW * 2)  // 14336 per group (single buffer)
#define SMEM_DYN (2 * XS_BYTES + 2 * AW_BYTES)   // 104448

__device__ __forceinline__ uint32_t prmt_hi(uint32_t a, uint32_t b) {
    uint32_t r; asm("prmt.b32 %0, %1, %2, 0x7632;" : "=r"(r) : "r"(a), "r"(b)); return r;
}
__device__ __forceinline__ uint32_t lo_pack2(float fx, float fy) {
    float h0 = __uint_as_float(__float_as_uint(fx) & 0xFFFF0000u);
    float h1 = __uint_as_float(__float_as_uint(fy) & 0xFFFF0000u);
    __nv_bfloat162 p = __floats2bfloat162_rn(fx - h0, fy - h1);
    return reinterpret_cast<uint32_t&>(p);
}
__device__ __forceinline__ void ldsm4(uint32_t& r0, uint32_t& r1, uint32_t& r2, uint32_t& r3,
                                      uint32_t a) {
    asm volatile("ldmatrix.sync.aligned.m8n8.x4.shared.b16 {%0,%1,%2,%3}, [%4];"
                 : "=r"(r0), "=r"(r1), "=r"(r2), "=r"(r3) : "r"(a));
}
__device__ __forceinline__ void mma16816(float* c,
                                         uint32_t a0, uint32_t a1, uint32_t a2, uint32_t a3,
                                         uint32_t b0, uint32_t b1) {
    asm volatile("mma.sync.aligned.m16n8k16.row.col.f32.bf16.bf16.f32 "
                 "{%0,%1,%2,%3}, {%4,%5,%6,%7}, {%8,%9}, {%0,%1,%2,%3};"
                 : "+f"(c[0]), "+f"(c[1]), "+f"(c[2]), "+f"(c[3])
                 : "r"(a0), "r"(a1), "r"(a2), "r"(a3), "r"(b0), "r"(b1));
}
__device__ __forceinline__ void gbar(int id) {   // group-local barrier (128 threads)
    asm volatile("bar.sync %0, 128;" :: "r"(id) : "memory");
}

__global__ __launch_bounds__(256, 2)
void lc_conv_mma3(const float* __restrict__ x, const float* __restrict__ wgt,
                  const float* __restrict__ bias, float* __restrict__ out)
{
    extern __shared__ char smem[];
    const int t  = threadIdx.x;
    const int g  = t >> 7;            // position group 0/1
    const int tg = t & 127;
    const int wid = tg >> 5, lane = t & 31;
    const int gid = lane >> 2, tig = lane & 3;

    const int bx = blockIdx.x, h = blockIdx.y;
    const int w0 = bx * 2;
    const int w  = w0 + g;

    __nv_bfloat16* xsg = (__nv_bfloat16*)(smem + g * XS_BYTES);       // this group's B tile
    char* awg = smem + 2 * XS_BYTES + g * AW_BYTES;                    // this group's A buffer

    // ---- W staging geometry (per group, 128 threads, 6 float4 units/chunk) ----
    const float* wpos = wgt + (size_t)(h * OW_ + w) * COUT_ * KTOT;
    int g_off[6], s_hi[6];
#pragma unroll
    for (int i = 0; i < 6; i++) {
        int u = tg + 128 * i;
        int row = u / 12, q = u - 12 * row;
        g_off[i] = row * KTOT + 4 * q;
        s_hi[i]  = (row * AROW + 4 * q) * 2;
    }

    // prefetch W chunk 0 (latency overlaps X staging)
    float4 rv[6];
#pragma unroll
    for (int i = 0; i < 6; i++) rv[i] = *(const float4*)(wpos + g_off[i]);

    // ---- X staging: all 256 threads; 4-lane groups share one (b,ci) row sliver ----
    {
        __nv_bfloat16* x0 = (__nv_bfloat16*)(smem);             // group0 tile
        __nv_bfloat16* x1 = (__nv_bfloat16*)(smem + XS_BYTES);  // group1 tile
        const int jj = t & 3;                  // column within sliver: col = w0-1+jj
        const int col = w0 - 1 + jj;
        const bool colok = (unsigned)col < IW_;
#pragma unroll 4
        for (int pass = 0; pass < 48; pass++) {
            int u  = pass * 64 + (t >> 2);
            int b  = u & 31;
            int ci = u >> 5;
            int c  = ci / 3, i = ci - 3 * c;
            int row = h + i - 1;
            float v = 0.f;
            if (colok && (unsigned)row < IH_)
                v = x[(((size_t)b * CIN_ + c) * IH_ + row) * IW_ + col];
            uint32_t ub = __float_as_uint(v);
            unsigned short hs = (unsigned short)(ub >> 16);            // truncate-hi
            float hf = __uint_as_float(ub & 0xFFFF0000u);
            __nv_bfloat16 lo = __float2bfloat16(v - hf);               // rn-lo
            __nv_bfloat16 hi = reinterpret_cast<__nv_bfloat16&>(hs);
            int k = 3 * ci;
            if (jj < 3) {          // group 0 uses cols w0-1..w0+1 as j=jj
                x0[(size_t)b * KROW + k + jj]        = hi;
                x0[(size_t)(b + 32) * KROW + k + jj] = lo;
            }
            if (jj >= 1) {         // group 1 uses cols w0..w0+2 as j=jj-1
                x1[(size_t)b * KROW + k + jj - 1]        = hi;
                x1[(size_t)(b + 32) * KROW + k + jj - 1] = lo;
            }
        }
    }

    // ---- store W chunk 0 ----
#pragma unroll
    for (int i = 0; i < 6; i++) {
        uint32_t h0 = prmt_hi(__float_as_uint(rv[i].x), __float_as_uint(rv[i].y));
        uint32_t h1 = prmt_hi(__float_as_uint(rv[i].z), __float_as_uint(rv[i].w));
        uint32_t l0 = lo_pack2(rv[i].x, rv[i].y);
        uint32_t l1 = lo_pack2(rv[i].z, rv[i].w);
        *(uint2*)(awg + s_hi[i])                 = make_uint2(h0, h1);
        *(uint2*)(awg + s_hi[i] + 64 * AROW * 2) = make_uint2(l0, l1);
    }
    __syncthreads();    // X tiles + both A chunk0 visible

    // ---- LDSM lane addressing ----
    uint32_t lds_b[4];
    {
        uint32_t base = (uint32_t)__cvta_generic_to_shared(xsg);
        int nrow = 8 * ((lane >> 4) & 1) + (lane & 7);
        int kadd = 8 * ((lane >> 3) & 1);
#pragma unroll
        for (int jp = 0; jp < 4; jp++)
            lds_b[jp] = base + (uint32_t)(16 * jp + nrow) * (KROW * 2) + kadd * 2;
    }
    uint32_t abase;
    {
        int arow = (wid * 16) + (lane & 7) + 8 * ((lane >> 3) & 1);
        int ak16 = (lane >> 4) & 1;
        abase = (uint32_t)__cvta_generic_to_shared(awg)
              + (uint32_t)arow * (AROW * 2) + (uint32_t)ak16 * 16;
    }

    float acc1[8][4];   // Wh x n-tiles 0..7 (Xh | Xl)
    float acc2[4][4];   // Wl x n-tiles 0..3 (Xh)
#pragma unroll
    for (int j = 0; j < 8; j++)
#pragma unroll
        for (int q = 0; q < 4; q++) acc1[j][q] = 0.f;
#pragma unroll
    for (int j = 0; j < 4; j++)
#pragma unroll
        for (int q = 0; q < 4; q++) acc2[j][q] = 0.f;

    const int barid = 1 + g;

    // ---- main loop over 48-k chunks (single A buffer, group-local bars) ----
#pragma unroll 1
    for (int ck = 0; ck < NCHK; ck++) {
        if (ck + 1 < NCHK) {
            int k0 = (ck + 1) * KC;
#pragma unroll
            for (int i = 0; i < 6; i++) rv[i] = *(const float4*)(wpos + g_off[i] + k0);
        }

#pragma unroll
        for (int s = 0; s < 3; s++) {
            uint32_t ah0, ah1, ah2, ah3, al0, al1, al2, al3;
            ldsm4(ah0, ah1, ah2, ah3, abase + s * 32);
            ldsm4(al0, al1, al2, al3, abase + 64 * (AROW * 2) + s * 32);

            uint32_t bb[16];
            uint32_t koff = (uint32_t)(ck * 3 + s) * 32;
#pragma unroll
            for (int jp = 0; jp < 4; jp++)
                ldsm4(bb[4 * jp], bb[4 * jp + 1], bb[4 * jp + 2], bb[4 * jp + 3],
                      lds_b[jp] + koff);

#pragma unroll
            for (int j = 0; j < 8; j++) {
                uint32_t b0 = bb[(j >> 1) * 4 + (j & 1) * 2];
                uint32_t b1 = bb[(j >> 1) * 4 + (j & 1) * 2 + 1];
                mma16816(acc1[j], ah0, ah1, ah2, ah3, b0, b1);
            }
#pragma unroll
            for (int j = 0; j < 4; j++) {
                uint32_t b0 = bb[(j >> 1) * 4 + (j & 1) * 2];
                uint32_t b1 = bb[(j >> 1) * 4 + (j & 1) * 2 + 1];
                mma16816(acc2[j], al0, al1, al2, al3, b0, b1);
            }
        }

        if (ck + 1 < NCHK) {
            gbar(barid);                      // all group warps done reading chunk ck
#pragma unroll
            for (int i = 0; i < 6; i++) {
                uint32_t h0 = prmt_hi(__float_as_uint(rv[i].x), __float_as_uint(rv[i].y));
                uint32_t h1 = prmt_hi(__float_as_uint(rv[i].z), __float_as_uint(rv[i].w));
                uint32_t l0 = lo_pack2(rv[i].x, rv[i].y);
                uint32_t l1 = lo_pack2(rv[i].z, rv[i].w);
                *(uint2*)(awg + s_hi[i])                 = make_uint2(h0, h1);
                *(uint2*)(awg + s_hi[i] + 64 * AROW * 2) = make_uint2(l0, l1);
            }
            gbar(barid);                      // chunk ck+1 visible
        }
    }

    // ---- epilogue: combine + bias, store ----
    const int o_lo = wid * 16 + gid;
    const int o_hi = o_lo + 8;
    const float bias_lo = bias[(o_lo * OH_ + h) * OW_ + w];
    const float bias_hi = bias[(o_hi * OH_ + h) * OW_ + w];

#pragma unroll
    for (int j = 0; j < 4; j++) {
        int b = 8 * j + 2 * tig;
        float v00 = acc1[j][0] + acc1[j + 4][0] + acc2[j][0] + bias_lo;
        float v01 = acc1[j][1] + acc1[j + 4][1] + acc2[j][1] + bias_lo;
        float v10 = acc1[j][2] + acc1[j + 4][2] + acc2[j][2] + bias_hi;
        float v11 = acc1[j][3] + acc1[j + 4][3] + acc2[j][3] + bias_hi;
        size_t p00 = (((size_t)b * COUT_ + o_lo) * OH_ + h) * OW_ + w;
        size_t p01 = (((size_t)(b + 1) * COUT_ + o_lo) * OH_ + h) * OW_ + w;
        out[p00] = v00;
        out[p01] = v01;
        out[p00 + (size_t)8 * OH_ * OW_] = v10;
        out[p01 + (size_t)8 * OH_ * OW_] = v11;
    }
}

extern "C" void kernel_launch(void* const* d_in, const int* in_sizes, int n_in,
                              void* d_out, int out_size)
{
    const float* x    = (const float*)d_in[0];   // [32,32,64,64]
    const float* wgt  = (const float*)d_in[1];   // [64,64,64,32,3,3]
    const float* bias = (const float*)d_in[2];   // [64,64,64]
    float* out = (float*)d_out;                  // [32,64,64,64]

    cudaFuncSetAttribute(lc_conv_mma3, cudaFuncAttributeMaxDynamicSharedMemorySize, SMEM_DYN);
    dim3 grid(OW_ / 2, OH_);
    lc_conv_mma3<<<grid, 256, SMEM_DYN>>>(x, wgt, bias, out);
}

// round 12
// speedup vs baseline: 1.7050x; 1.0707x over previous
#include <cuda_runtime.h>
#include <cuda_bf16.h>
#include <cstdint>

// Locally-connected conv via mma.sync bf16 split precision.
// CTA = 256 threads = 2 position-groups (w0, w0+1), sharing X staging.
// Weights streamed via cp.async (3-deep fp32 ring, 18 stages of k=16);
// A-fragments built directly from fp32 smem (no bf16 A tile / A ldmatrix).
// Out = WhXh + WhXl + WlXh (+bias); dropped WlXl ~ 2^-17.

#define B_    32
#define CIN_  32
#define IH_   64
#define IW_   64
#define COUT_ 64
#define OH_   64
#define OW_   64
#define KTOT  288
#define KROW  296               // B tile row stride (bf16) = 592 B, LDSM conflict-free
#define NST   18                // k16 stages
#define SROW  20                // ring row stride (floats) = 80 B
#define STAGE_B (64 * SROW * 4) // 5120 B per stage
#define NBUF  3

#define XS_BYTES (64 * KROW * 2)          // 37888 per group
#define RING_BYTES (NBUF * STAGE_B)       // 15360 per group
#define SMEM_DYN (2 * XS_BYTES + 2 * RING_BYTES)   // 106496

__device__ __forceinline__ uint32_t prmt_hi(uint32_t a, uint32_t b) {
    uint32_t r; asm("prmt.b32 %0, %1, %2, 0x7632;" : "=r"(r) : "r"(a), "r"(b)); return r;
}
__device__ __forceinline__ uint32_t lo_pack2(float fx, float fy) {
    float h0 = __uint_as_float(__float_as_uint(fx) & 0xFFFF0000u);
    float h1 = __uint_as_float(__float_as_uint(fy) & 0xFFFF0000u);
    __nv_bfloat162 p = __floats2bfloat162_rn(fx - h0, fy - h1);
    return reinterpret_cast<uint32_t&>(p);
}
__device__ __forceinline__ void ldsm4(uint32_t& r0, uint32_t& r1, uint32_t& r2, uint32_t& r3,
                                      uint32_t a) {
    asm volatile("ldmatrix.sync.aligned.m8n8.x4.shared.b16 {%0,%1,%2,%3}, [%4];"
                 : "=r"(r0), "=r"(r1), "=r"(r2), "=r"(r3) : "r"(a));
}
__device__ __forceinline__ float2 lds_f2(uint32_t a) {
    float2 v; asm("ld.shared.v2.f32 {%0,%1}, [%2];" : "=f"(v.x), "=f"(v.y) : "r"(a));
    return v;
}
__device__ __forceinline__ void mma16816(float* c,
                                         uint32_t a0, uint32_t a1, uint32_t a2, uint32_t a3,
                                         uint32_t b0, uint32_t b1) {
    asm volatile("mma.sync.aligned.m16n8k16.row.col.f32.bf16.bf16.f32 "
                 "{%0,%1,%2,%3}, {%4,%5,%6,%7}, {%8,%9}, {%0,%1,%2,%3};"
                 : "+f"(c[0]), "+f"(c[1]), "+f"(c[2]), "+f"(c[3])
                 : "r"(a0), "r"(a1), "r"(a2), "r"(a3), "r"(b0), "r"(b1));
}
__device__ __forceinline__ void gbar(int id) {
    asm volatile("bar.sync %0, 128;" :: "r"(id) : "memory");
}
__device__ __forceinline__ void issue_stage(uint32_t ring_buf, const float* wpos,
                                            int tg, int k0) {
#pragma unroll
    for (int i = 0; i < 2; i++) {
        int u = tg + 128 * i;
        int row = u >> 2, q = u & 3;
        const float* g = wpos + row * KTOT + k0 + 4 * q;
        uint32_t d = ring_buf + (uint32_t)(row * SROW + 4 * q) * 4u;
        asm volatile("cp.async.cg.shared.global [%0], [%1], 16;" :: "r"(d), "l"(g));
    }
    asm volatile("cp.async.commit_group;" ::: "memory");
}

__global__ __launch_bounds__(256, 2)
void lc_conv_mma4(const float* __restrict__ x, const float* __restrict__ wgt,
                  const float* __restrict__ bias, float* __restrict__ out)
{
    extern __shared__ char smem[];
    const int t  = threadIdx.x;
    const int g  = t >> 7;            // position group 0/1
    const int tg = t & 127;
    const int wid = tg >> 5, lane = t & 31;
    const int gid = lane >> 2, tig = lane & 3;

    const int bx = blockIdx.x, h = blockIdx.y;
    const int w0 = bx * 2;
    const int w  = w0 + g;

    __nv_bfloat16* xsg = (__nv_bfloat16*)(smem + g * XS_BYTES);
    const uint32_t ring = (uint32_t)__cvta_generic_to_shared(smem)
                        + 2u * XS_BYTES + (uint32_t)g * RING_BYTES;

    const float* wpos = wgt + (size_t)(h * OW_ + w) * COUT_ * KTOT;

    // ---- prologue: issue first 3 weight stages (land during X staging) ----
    issue_stage(ring + 0 * STAGE_B, wpos, tg, 0 * 16);
    issue_stage(ring + 1 * STAGE_B, wpos, tg, 1 * 16);
    issue_stage(ring + 2 * STAGE_B, wpos, tg, 2 * 16);

    // ---- X staging: 4-lane cooperative, hi/lo split, both group tiles ----
    {
        __nv_bfloat16* x0 = (__nv_bfloat16*)(smem);
        __nv_bfloat16* x1 = (__nv_bfloat16*)(smem + XS_BYTES);
        const int jj = t & 3;
        const int col = w0 - 1 + jj;
        const bool colok = (unsigned)col < IW_;
#pragma unroll 8
        for (int pass = 0; pass < 48; pass++) {
            int u  = pass * 64 + (t >> 2);
            int b  = u & 31;
            int ci = u >> 5;
            int c  = ci / 3, i = ci - 3 * c;
            int row = h + i - 1;
            float v = 0.f;
            if (colok && (unsigned)row < IH_)
                v = x[(((size_t)b * CIN_ + c) * IH_ + row) * IW_ + col];
            uint32_t ub = __float_as_uint(v);
            unsigned short hs = (unsigned short)(ub >> 16);
            float hf = __uint_as_float(ub & 0xFFFF0000u);
            __nv_bfloat16 lo = __float2bfloat16(v - hf);
            __nv_bfloat16 hi = reinterpret_cast<__nv_bfloat16&>(hs);
            int k = 3 * ci;
            if (jj < 3) {
                x0[(size_t)b * KROW + k + jj]        = hi;
                x0[(size_t)(b + 32) * KROW + k + jj] = lo;
            }
            if (jj >= 1) {
                x1[(size_t)b * KROW + k + jj - 1]        = hi;
                x1[(size_t)(b + 32) * KROW + k + jj - 1] = lo;
            }
        }
    }
    __syncthreads();    // X tiles visible to both groups

    // ---- lane addressing ----
    uint32_t lds_b[4];
    {
        uint32_t base = (uint32_t)__cvta_generic_to_shared(xsg);
        int nrow = 8 * ((lane >> 4) & 1) + (lane & 7);
        int kadd = 8 * ((lane >> 3) & 1);
#pragma unroll
        for (int jp = 0; jp < 4; jp++)
            lds_b[jp] = base + (uint32_t)(16 * jp + nrow) * (KROW * 2) + kadd * 2;
    }
    // A-fragment addresses within a stage: (r0, c0) quad
    const uint32_t a00o = (uint32_t)((wid * 16 + gid) * SROW + 2 * tig) * 4u;
    const uint32_t a10o = a00o + 8u * SROW * 4u;

    float acc1[8][4];   // Wh x n-tiles 0..7 (Xh | Xl)
    float acc2[4][4];   // Wl x n-tiles 0..3 (Xh)
#pragma unroll
    for (int j = 0; j < 8; j++)
#pragma unroll
        for (int q = 0; q < 4; q++) acc1[j][q] = 0.f;
#pragma unroll
    for (int j = 0; j < 4; j++)
#pragma unroll
        for (int q = 0; q < 4; q++) acc2[j][q] = 0.f;

    const int barid = 1 + g;
    int bufo = 0;

    // ---- main loop: 18 k16 stages ----
#pragma unroll 1
    for (int ck = 0; ck < NST; ck++) {
        if (ck + 2 < NST)       asm volatile("cp.async.wait_group 2;" ::: "memory");
        else if (ck + 2 == NST) asm volatile("cp.async.wait_group 1;" ::: "memory");
        else                    asm volatile("cp.async.wait_group 0;" ::: "memory");
        gbar(barid);            // stage ck landed & visible to the group

        const uint32_t sA = ring + (uint32_t)bufo * STAGE_B;

        // A fragments from fp32 ring
        float2 f00 = lds_f2(sA + a00o);
        float2 f10 = lds_f2(sA + a10o);
        float2 f01 = lds_f2(sA + a00o + 32);
        float2 f11 = lds_f2(sA + a10o + 32);
        uint32_t ah0 = prmt_hi(__float_as_uint(f00.x), __float_as_uint(f00.y));
        uint32_t ah1 = prmt_hi(__float_as_uint(f10.x), __float_as_uint(f10.y));
        uint32_t ah2 = prmt_hi(__float_as_uint(f01.x), __float_as_uint(f01.y));
        uint32_t ah3 = prmt_hi(__float_as_uint(f11.x), __float_as_uint(f11.y));
        uint32_t al0 = lo_pack2(f00.x, f00.y);
        uint32_t al1 = lo_pack2(f10.x, f10.y);
        uint32_t al2 = lo_pack2(f01.x, f01.y);
        uint32_t al3 = lo_pack2(f11.x, f11.y);

        // B fragments
        uint32_t bb[16];
        uint32_t koff = (uint32_t)ck * 32;
#pragma unroll
        for (int jp = 0; jp < 4; jp++)
            ldsm4(bb[4 * jp], bb[4 * jp + 1], bb[4 * jp + 2], bb[4 * jp + 3],
                  lds_b[jp] + koff);

#pragma unroll
        for (int j = 0; j < 8; j++) {
            uint32_t b0 = bb[(j >> 1) * 4 + (j & 1) * 2];
            uint32_t b1 = bb[(j >> 1) * 4 + (j & 1) * 2 + 1];
            mma16816(acc1[j], ah0, ah1, ah2, ah3, b0, b1);
        }
#pragma unroll
        for (int j = 0; j < 4; j++) {
            uint32_t b0 = bb[(j >> 1) * 4 + (j & 1) * 2];
            uint32_t b1 = bb[(j >> 1) * 4 + (j & 1) * 2 + 1];
            mma16816(acc2[j], al0, al1, al2, al3, b0, b1);
        }

        gbar(barid);            // whole group done reading this buffer
        if (ck + NBUF < NST)
            issue_stage(sA, wpos, tg, (ck + NBUF) * 16);
        bufo = (bufo == NBUF - 1) ? 0 : bufo + 1;
    }

    // ---- epilogue: combine + bias, store ----
    const int o_lo = wid * 16 + gid;
    const int o_hi = o_lo + 8;
    const float bias_lo = bias[(o_lo * OH_ + h) * OW_ + w];
    const float bias_hi = bias[(o_hi * OH_ + h) * OW_ + w];

#pragma unroll
    for (int j = 0; j < 4; j++) {
        int b = 8 * j + 2 * tig;
        float v00 = acc1[j][0] + acc1[j + 4][0] + acc2[j][0] + bias_lo;
        float v01 = acc1[j][1] + acc1[j + 4][1] + acc2[j][1] + bias_lo;
        float v10 = acc1[j][2] + acc1[j + 4][2] + acc2[j][2] + bias_hi;
        float v11 = acc1[j][3] + acc1[j + 4][3] + acc2[j][3] + bias_hi;
        size_t p00 = (((size_t)b * COUT_ + o_lo) * OH_ + h) * OW_ + w;
        size_t p01 = (((size_t)(b + 1) * COUT_ + o_lo) * OH_ + h) * OW_ + w;
        out[p00] = v00;
        out[p01] = v01;
        out[p00 + (size_t)8 * OH_ * OW_] = v10;
        out[p01 + (size_t)8 * OH_ * OW_] = v11;
    }
}

extern "C" void kernel_launch(void* const* d_in, const int* in_sizes, int n_in,
                              void* d_out, int out_size)
{
    const float* x    = (const float*)d_in[0];   // [32,32,64,64]
    const float* wgt  = (const float*)d_in[1];   // [64,64,64,32,3,3]
    const float* bias = (const float*)d_in[2];   // [64,64,64]
    float* out = (float*)d_out;                  // [32,64,64,64]

    cudaFuncSetAttribute(lc_conv_mma4, cudaFuncAttributeMaxDynamicSharedMemorySize, SMEM_DYN);
    dim3 grid(OW_ / 2, OH_);
    lc_conv_mma4<<<grid, 256, SMEM_DYN>>>(x, wgt, bias, out);
}

// round 15
// speedup vs baseline: 1.7464x; 1.0243x over previous
#include <cuda_runtime.h>
#include <cuda_bf16.h>
#include <cstdint>

// Locally-connected conv via mma.sync bf16 split precision.
// CTA = 256 threads = 2 position-groups (w0, w0+1), sharing X staging.
// Weights: WARP-PRIVATE cp.async rings (each warp streams its own 16 W rows,
// 3-deep, 18 k16 stages). Zero barriers in the main loop — warps free-run.
// X tile: padded rows (KROW=296), R9-verified conflict-free ldmatrix.
// Out = WhXh + WhXl + WlXh (+bias); dropped WlXl ~ 2^-17.

#define B_    32
#define CIN_  32
#define IH_   64
#define IW_   64
#define COUT_ 64
#define OH_   64
#define OW_   64
#define KTOT  288
#define KROW  296               // X tile row stride (bf16) = 592 B
#define NST   18                // k16 stages
#define SROW  20                // ring row stride (floats) = 80 B
#define WSTG  (16 * SROW * 4)   // 1280 B per warp per stage
#define NBUF  3

#define XS_BYTES (64 * KROW * 2)            // 37888 per group
#define RING_BYTES (NBUF * WSTG)            // 3840 per warp
#define SMEM_DYN (2 * XS_BYTES + 8 * RING_BYTES)   // 106496 -> 2 CTAs/SM

__device__ __forceinline__ uint32_t prmt_hi(uint32_t a, uint32_t b) {
    uint32_t r; asm("prmt.b32 %0, %1, %2, 0x7632;" : "=r"(r) : "r"(a), "r"(b)); return r;
}
__device__ __forceinline__ uint32_t lo_pack2(float fx, float fy) {
    float h0 = __uint_as_float(__float_as_uint(fx) & 0xFFFF0000u);
    float h1 = __uint_as_float(__float_as_uint(fy) & 0xFFFF0000u);
    __nv_bfloat162 p = __floats2bfloat162_rn(fx - h0, fy - h1);
    return reinterpret_cast<uint32_t&>(p);
}
__device__ __forceinline__ void ldsm4(uint32_t& r0, uint32_t& r1, uint32_t& r2, uint32_t& r3,
                                      uint32_t a) {
    asm volatile("ldmatrix.sync.aligned.m8n8.x4.shared.b16 {%0,%1,%2,%3}, [%4];"
                 : "=r"(r0), "=r"(r1), "=r"(r2), "=r"(r3) : "r"(a));
}
__device__ __forceinline__ float2 lds_f2(uint32_t a) {
    float2 v; asm("ld.shared.v2.f32 {%0,%1}, [%2];" : "=f"(v.x), "=f"(v.y) : "r"(a));
    return v;
}
__device__ __forceinline__ void mma16816(float* c,
                                         uint32_t a0, uint32_t a1, uint32_t a2, uint32_t a3,
                                         uint32_t b0, uint32_t b1) {
    asm volatile("mma.sync.aligned.m16n8k16.row.col.f32.bf16.bf16.f32 "
                 "{%0,%1,%2,%3}, {%4,%5,%6,%7}, {%8,%9}, {%0,%1,%2,%3};"
                 : "+f"(c[0]), "+f"(c[1]), "+f"(c[2]), "+f"(c[3])
                 : "r"(a0), "r"(a1), "r"(a2), "r"(a3), "r"(b0), "r"(b1));
}
// Warp-private stage copy: this warp's 16 W rows, k16 slice [k0, k0+16).
// Unit u in [0,64): row = u>>2, 16B chunk = u&3. Lane does u = lane, lane+32.
__device__ __forceinline__ void issue_stage_w(uint32_t buf, const float* wrow,
                                              int lane, int k0) {
#pragma unroll
    for (int i = 0; i < 2; i++) {
        int u = lane + 32 * i;
        int row = u >> 2, q = u & 3;
        const float* src = wrow + row * KTOT + k0 + 4 * q;
        uint32_t dst = buf + (uint32_t)(row * SROW + 4 * q) * 4u;
        asm volatile("cp.async.cg.shared.global [%0], [%1], 16;" :: "r"(dst), "l"(src));
    }
    asm volatile("cp.async.commit_group;" ::: "memory");
}

__global__ __launch_bounds__(256, 2)
void lc_conv_mma6(const float* __restrict__ x, const float* __restrict__ wgt,
                  const float* __restrict__ bias, float* __restrict__ out)
{
    extern __shared__ char smem[];
    const int t  = threadIdx.x;
    const int g  = t >> 7;            // position group 0/1
    const int tg = t & 127;
    const int wid = tg >> 5, lane = t & 31;
    const int gid = lane >> 2, tig = lane & 3;

    const int bx = blockIdx.x, h = blockIdx.y;
    const int w0 = bx * 2;
    const int w  = w0 + g;

    __nv_bfloat16* xsg = (__nv_bfloat16*)(smem + g * XS_BYTES);
    const uint32_t ring = (uint32_t)__cvta_generic_to_shared(smem)
                        + 2u * XS_BYTES + (uint32_t)(g * 4 + wid) * RING_BYTES;

    // this warp's 16 weight rows for its position
    const float* wrow = wgt + ((size_t)(h * OW_ + w) * COUT_ + wid * 16) * KTOT;

    // ---- prologue: issue stages 0,1 into private ring (land during X staging) ----
    issue_stage_w(ring + 0 * WSTG, wrow, lane, 0 * 16);
    issue_stage_w(ring + 1 * WSTG, wrow, lane, 1 * 16);

    // ---- X staging: 4-lane cooperative, hi/lo split, both group tiles ----
    {
        __nv_bfloat16* x0 = (__nv_bfloat16*)(smem);
        __nv_bfloat16* x1 = (__nv_bfloat16*)(smem + XS_BYTES);
        const int jj = t & 3;
        const int col = w0 - 1 + jj;
        const bool colok = (unsigned)col < IW_;
#pragma unroll 8
        for (int pass = 0; pass < 48; pass++) {
            int u  = pass * 64 + (t >> 2);
            int b  = u & 31;
            int ci = u >> 5;
            int c  = ci / 3, i = ci - 3 * c;
            int row = h + i - 1;
            float v = 0.f;
            if (colok && (unsigned)row < IH_)
                v = x[(((size_t)b * CIN_ + c) * IH_ + row) * IW_ + col];
            uint32_t ub = __float_as_uint(v);
            unsigned short hs = (unsigned short)(ub >> 16);
            float hf = __uint_as_float(ub & 0xFFFF0000u);
            __nv_bfloat16 lo = __float2bfloat16(v - hf);
            __nv_bfloat16 hi = reinterpret_cast<__nv_bfloat16&>(hs);
            int k = 3 * ci;
            if (jj < 3) {
                x0[(size_t)b * KROW + k + jj]        = hi;
                x0[(size_t)(b + 32) * KROW + k + jj] = lo;
            }
            if (jj >= 1) {
                x1[(size_t)b * KROW + k + jj - 1]        = hi;
                x1[(size_t)(b + 32) * KROW + k + jj - 1] = lo;
            }
        }
    }
    __syncthreads();    // X tiles visible; last barrier until epilogue

    // ---- lane addressing ----
    uint32_t lds_b[4];
    {
        uint32_t base = (uint32_t)__cvta_generic_to_shared(xsg);
        int nrow = 8 * ((lane >> 4) & 1) + (lane & 7);
        int kadd = 8 * ((lane >> 3) & 1);
#pragma unroll
        for (int jp = 0; jp < 4; jp++)
            lds_b[jp] = base + (uint32_t)(16 * jp + nrow) * (KROW * 2) + kadd * 2;
    }
    // A fragments within this warp's private stage buffer
    const uint32_t a00o = (uint32_t)(gid * SROW + 2 * tig) * 4u;
    const uint32_t a10o = a00o + 8u * SROW * 4u;

    float acc1[8][4];   // Wh x n-tiles 0..7 (Xh | Xl)
    float acc2[4][4];   // Wl x n-tiles 0..3 (Xh)
#pragma unroll
    for (int j = 0; j < 8; j++)
#pragma unroll
        for (int q = 0; q < 4; q++) acc1[j][q] = 0.f;
#pragma unroll
    for (int j = 0; j < 4; j++)
#pragma unroll
        for (int q = 0; q < 4; q++) acc2[j][q] = 0.f;

    // ---- main loop: 18 k16 stages, no barriers, self-paced per warp ----
#pragma unroll 1
    for (int ck = 0; ck < NST; ck++) {
        // issue stage ck+2 into buffer (ck+2)%3 (this warp consumed it at ck-1)
        if (ck + 2 < NST)
            issue_stage_w(ring + (uint32_t)((ck + 2) % NBUF) * WSTG,
                          wrow, lane, (ck + 2) * 16);
        // wait until stage ck landed (FIFO group completion, per-thread state)
        if (ck + 3 <= NST)      asm volatile("cp.async.wait_group 2;" ::: "memory");
        else if (ck + 2 == NST) asm volatile("cp.async.wait_group 1;" ::: "memory");
        else                    asm volatile("cp.async.wait_group 0;" ::: "memory");

        const uint32_t sA = ring + (uint32_t)(ck % NBUF) * WSTG;

        // A fragments from private fp32 ring
        float2 f00 = lds_f2(sA + a00o);
        float2 f10 = lds_f2(sA + a10o);
        float2 f01 = lds_f2(sA + a00o + 32);
        float2 f11 = lds_f2(sA + a10o + 32);
        uint32_t ah0 = prmt_hi(__float_as_uint(f00.x), __float_as_uint(f00.y));
        uint32_t ah1 = prmt_hi(__float_as_uint(f10.x), __float_as_uint(f10.y));
        uint32_t ah2 = prmt_hi(__float_as_uint(f01.x), __float_as_uint(f01.y));
        uint32_t ah3 = prmt_hi(__float_as_uint(f11.x), __float_as_uint(f11.y));
        uint32_t al0 = lo_pack2(f00.x, f00.y);
        uint32_t al1 = lo_pack2(f10.x, f10.y);
        uint32_t al2 = lo_pack2(f01.x, f01.y);
        uint32_t al3 = lo_pack2(f11.x, f11.y);

        // B fragments
        uint32_t bb[16];
        uint32_t koff = (uint32_t)ck * 32;
#pragma unroll
        for (int jp = 0; jp < 4; jp++)
            ldsm4(bb[4 * jp], bb[4 * jp + 1], bb[4 * jp + 2], bb[4 * jp + 3],
                  lds_b[jp] + koff);

#pragma unroll
        for (int j = 0; j < 8; j++) {
            uint32_t b0 = bb[(j >> 1) * 4 + (j & 1) * 2];
            uint32_t b1 = bb[(j >> 1) * 4 + (j & 1) * 2 + 1];
            mma16816(acc1[j], ah0, ah1, ah2, ah3, b0, b1);
        }
#pragma unroll
        for (int j = 0; j < 4; j++) {
            uint32_t b0 = bb[(j >> 1) * 4 + (j & 1) * 2];
            uint32_t b1 = bb[(j >> 1) * 4 + (j & 1) * 2 + 1];
            mma16816(acc2[j], al0, al1, al2, al3, b0, b1);
        }
    }

    // ---- epilogue: combine + bias, store ----
    const int o_lo = wid * 16 + gid;
    const int o_hi = o_lo + 8;
    const float bias_lo = bias[(o_lo * OH_ + h) * OW_ + w];
    const float bias_hi = bias[(o_hi * OH_ + h) * OW_ + w];

#pragma unroll
    for (int j = 0; j < 4; j++) {
        int b = 8 * j + 2 * tig;
        float v00 = acc1[j][0] + acc1[j + 4][0] + acc2[j][0] + bias_lo;
        float v01 = acc1[j][1] + acc1[j + 4][1] + acc2[j][1] + bias_lo;
        float v10 = acc1[j][2] + acc1[j + 4][2] + acc2[j][2] + bias_hi;
        float v11 = acc1[j][3] + acc1[j + 4][3] + acc2[j][3] + bias_hi;
        size_t p00 = (((size_t)b * COUT_ + o_lo) * OH_ + h) * OW_ + w;
        size_t p01 = (((size_t)(b + 1) * COUT_ + o_lo) * OH_ + h) * OW_ + w;
        out[p00] = v00;
        out[p01] = v01;
        out[p00 + (size_t)8 * OH_ * OW_] = v10;
        out[p01 + (size_t)8 * OH_ * OW_] = v11;
    }
}

extern "C" void kernel_launch(void* const* d_in, const int* in_sizes, int n_in,
                              void* d_out, int out_size)
{
    const float* x    = (const float*)d_in[0];   // [32,32,64,64]
    const float* wgt  = (const float*)d_in[1];   // [64,64,64,32,3,3]
    const float* bias = (const float*)d_in[2];   // [64,64,64]
    float* out = (float*)d_out;                  // [32,64,64,64]

    cudaFuncSetAttribute(lc_conv_mma6, cudaFuncAttributeMaxDynamicSharedMemorySize, SMEM_DYN);
    dim3 grid(OW_ / 2, OH_);
    lc_conv_mma6<<<grid, 256, SMEM_DYN>>>(x, wgt, bias, out);
}